// round 2
// baseline (speedup 1.0000x reference)
#include <cuda_runtime.h>
#include <cuda_bf16.h>
#include <cstdint>
#include <math.h>

// ---------------- problem constants ----------------
#define BATCH 16
#define SEQ   512
#define HU    512          // hidden units per direction
#define DIN   1024
#define MTOT  (SEQ*BATCH)  // 8192 rows, m = s*16 + b
#define NXG   4096         // 2 dirs * 4 gates * 512
#define HIDN  1024
#define KDIM  1024

// ---------------- device scratch (no runtime allocation) ----------------
__device__ float g_X0[(size_t)MTOT * DIN];
__device__ float g_XG[(size_t)MTOT * NXG];   // layout [s][n(4096)][b(16)]
__device__ float g_Y [(size_t)MTOT * HIDN];  // [m][dir*512+u]
__device__ float g_A1[(size_t)MTOT * HIDN];
__device__ float g_A2[(size_t)MTOT * HIDN];
__device__ float g_bXG[NXG];
__device__ float g_h[2][2][BATCH][HU];       // [parity][dir][b][k]
__device__ unsigned g_bar;

// ---------------- helpers ----------------
__device__ __forceinline__ unsigned f2tf(float x) {
    unsigned r;
    asm("cvt.rna.tf32.f32 %0, %1;" : "=r"(r) : "f"(x));
    return r;
}
__device__ __forceinline__ void mma_tf32(float& c0, float& c1, float& c2, float& c3,
                                         unsigned a0, unsigned a1, unsigned a2, unsigned a3,
                                         unsigned b0, unsigned b1) {
    asm volatile(
        "mma.sync.aligned.m16n8k8.row.col.f32.tf32.tf32.f32 "
        "{%0,%1,%2,%3},{%4,%5,%6,%7},{%8,%9},{%0,%1,%2,%3};"
        : "+f"(c0), "+f"(c1), "+f"(c2), "+f"(c3)
        : "r"(a0), "r"(a1), "r"(a2), "r"(a3), "r"(b0), "r"(b1));
}
__device__ __forceinline__ void cp16(void* smem, const void* gmem) {
    unsigned s = (unsigned)__cvta_generic_to_shared(smem);
    asm volatile("cp.async.ca.shared.global [%0], [%1], 16;" :: "r"(s), "l"(gmem));
}
__device__ __forceinline__ void cp_commit() { asm volatile("cp.async.commit_group;"); }
__device__ __forceinline__ void cp_wait1()  { asm volatile("cp.async.wait_group 1;"); }
__device__ __forceinline__ void cp_wait0()  { asm volatile("cp.async.wait_group 0;"); }

__device__ __forceinline__ float sigm(float x) { return 1.0f / (1.0f + __expf(-x)); }

__device__ __forceinline__ float* selbuf(int s) {
    switch (s) {
        case 0: return g_X0;
        case 1: return g_Y;
        case 2: return g_A1;
        case 3: return g_A2;
        default: return g_XG;
    }
}

// ---------------- k_pre: zero h state + barrier ----------------
__global__ void k_pre() {
    int tid = blockIdx.x * blockDim.x + threadIdx.x;
    float* p = &g_h[0][0][0][0];
    const int total = 2 * 2 * BATCH * HU;   // 32768
    if (tid < total) p[tid] = 0.f;
    if (tid == 0) g_bar = 0u;
}

// ---------------- k_bias: g_bXG = b_ih[l] + b_hh[l] ----------------
__global__ void k_bias(const float* __restrict__ bi, const float* __restrict__ bh) {
    int n = blockIdx.x * blockDim.x + threadIdx.x;
    if (n < NXG) g_bXG[n] = bi[n] + bh[n];
}

// ---------------- k_embed: X0[m] = [lang(768) | emb_table[x](256)] ----------------
__global__ void k_embed(const int* __restrict__ x, const float* __restrict__ lang,
                        const float* __restrict__ emb) {
    int m = blockIdx.x;           // m = s*16 + b
    int b = m & 15;
    int s = m >> 4;
    int t = threadIdx.x;          // 256 threads, one float4 each
    float4 v;
    if (t < 192) {
        v = *(const float4*)(lang + ((size_t)(b * SEQ + s)) * 768 + t * 4);
    } else {
        int tok = x[b * SEQ + s];
        v = *(const float4*)(emb + (size_t)tok * 256 + (t - 192) * 4);
    }
    *(float4*)(g_X0 + (size_t)m * DIN + t * 4) = v;
}

// ---------------- tf32 GEMM: C[m][n] = A[m][:] . W[n][:] + bias[n] ----------------
// A: [8192][1024] row-major.  W: [N][1024] row-major.  K = 1024 fixed.
// act: 0 none, 1 leaky_relu(0.01).  xg: 0 -> C row-major [m][N]; 1 -> XG layout.
#define ASTR 20   // smem row stride in floats (16 data + 4 pad, 16B-aligned, conflict-free)

__global__ __launch_bounds__(256, 1)
void k_gemm(int asel, const float* __restrict__ W, const float* __restrict__ bias_ext,
            int csel, int N, int act, int xg) {
    __shared__ float As[2][128 * ASTR];
    __shared__ float Bs[2][128 * ASTR];

    const float* A = selbuf(asel);
    float* C = selbuf(csel);
    const float* bias = bias_ext ? bias_ext : g_bXG;

    int m0 = blockIdx.y * 128;
    int n0 = blockIdx.x * 128;
    int tid = threadIdx.x, lane = tid & 31, warp = tid >> 5;
    int am = (warp >> 1) * 32;   // warp M offset within CTA tile (4 warps in M)
    int bn = (warp & 1) * 64;    // warp N offset (2 warps in N)

    float acc[2][8][4];
    #pragma unroll
    for (int i = 0; i < 2; i++)
        #pragma unroll
        for (int j = 0; j < 8; j++)
            #pragma unroll
            for (int q = 0; q < 4; q++) acc[i][j][q] = 0.f;

    // loader: 128 rows x 4 x 16B chunks per matrix, 256 threads -> 2 chunks each
    auto load_tiles = [&](int kk, int buf) {
        int k0 = kk * 16;
        #pragma unroll
        for (int c = 0; c < 2; c++) {
            int id = tid + c * 256;
            int row = id >> 2, ch = id & 3;
            cp16(&As[buf][row * ASTR + ch * 4], A + (size_t)(m0 + row) * KDIM + k0 + ch * 4);
        }
        #pragma unroll
        for (int c = 0; c < 2; c++) {
            int id = tid + c * 256;
            int row = id >> 2, ch = id & 3;
            cp16(&Bs[buf][row * ASTR + ch * 4], W + (size_t)(n0 + row) * KDIM + k0 + ch * 4);
        }
        cp_commit();
    };

    load_tiles(0, 0);

    #pragma unroll 1
    for (int kk = 0; kk < 64; kk++) {
        int buf = kk & 1;
        if (kk < 63) load_tiles(kk + 1, buf ^ 1);
        if (kk < 63) cp_wait1(); else cp_wait0();
        __syncthreads();

        #pragma unroll
        for (int kt = 0; kt < 2; kt++) {
            unsigned af[2][4];
            #pragma unroll
            for (int mt = 0; mt < 2; mt++) {
                int r = am + mt * 16 + (lane >> 2);
                int kc = kt * 8 + (lane & 3);
                af[mt][0] = f2tf(As[buf][r * ASTR + kc]);
                af[mt][1] = f2tf(As[buf][(r + 8) * ASTR + kc]);
                af[mt][2] = f2tf(As[buf][r * ASTR + kc + 4]);
                af[mt][3] = f2tf(As[buf][(r + 8) * ASTR + kc + 4]);
            }
            #pragma unroll
            for (int nt = 0; nt < 8; nt++) {
                int rn = bn + nt * 8 + (lane >> 2);
                int kc = kt * 8 + (lane & 3);
                unsigned b0 = f2tf(Bs[buf][rn * ASTR + kc]);
                unsigned b1 = f2tf(Bs[buf][rn * ASTR + kc + 4]);
                mma_tf32(acc[0][nt][0], acc[0][nt][1], acc[0][nt][2], acc[0][nt][3],
                         af[0][0], af[0][1], af[0][2], af[0][3], b0, b1);
                mma_tf32(acc[1][nt][0], acc[1][nt][1], acc[1][nt][2], acc[1][nt][3],
                         af[1][0], af[1][1], af[1][2], af[1][3], b0, b1);
            }
        }
        __syncthreads();
    }

    // epilogue
    #pragma unroll
    for (int mt = 0; mt < 2; mt++) {
        #pragma unroll
        for (int nt = 0; nt < 8; nt++) {
            int r = m0 + am + mt * 16 + (lane >> 2);
            int n = n0 + bn + nt * 8 + 2 * (lane & 3);
            float v0 = acc[mt][nt][0] + bias[n];
            float v1 = acc[mt][nt][1] + bias[n + 1];
            float v2 = acc[mt][nt][2] + bias[n];
            float v3 = acc[mt][nt][3] + bias[n + 1];
            if (act) {
                v0 = v0 > 0.f ? v0 : 0.01f * v0;
                v1 = v1 > 0.f ? v1 : 0.01f * v1;
                v2 = v2 > 0.f ? v2 : 0.01f * v2;
                v3 = v3 > 0.f ? v3 : 0.01f * v3;
            }
            if (xg) {
                int s1 = r >> 4, b1v = r & 15;
                int s2 = (r + 8) >> 4, b2v = (r + 8) & 15;
                C[((size_t)s1 * NXG + n) * 16 + b1v]       = v0;
                C[((size_t)s1 * NXG + n + 1) * 16 + b1v]   = v1;
                C[((size_t)s2 * NXG + n) * 16 + b2v]       = v2;
                C[((size_t)s2 * NXG + n + 1) * 16 + b2v]   = v3;
            } else {
                *(float2*)(C + (size_t)r * N + n)       = make_float2(v0, v1);
                *(float2*)(C + (size_t)(r + 8) * N + n) = make_float2(v2, v3);
            }
        }
    }
}

// ---------------- persistent bidirectional LSTM recurrence ----------------
// 128 CTAs x 128 threads. CTA c: dir = c>>6, units u0 = (c&63)*8.
// Warp w handles gate w (i,f,g,o), rows gate*512 + u0 .. +8, full K=512 in regs.
__global__ __launch_bounds__(128, 1)
void k_rec(const float* __restrict__ Whh /* [2][2048][512] for this layer */,
           const int* __restrict__ lengths) {
    __shared__ float hs[BATCH * 516 + 4];       // staged h (tf32-rounded), stride 516
    __shared__ float smg[4][BATCH][8];          // gate exchange

    int tid = threadIdx.x, lane = tid & 31, w = tid >> 5;
    int cta = blockIdx.x;
    int dir = cta >> 6;
    int u0 = (cta & 63) * 8;

    // load W_hh fragments into registers (stay for all 512 steps)
    const float* wrow = Whh + ((size_t)dir * 2048 + w * 512 + u0 + (lane >> 2)) * 512;
    unsigned wB[128];
    #pragma unroll
    for (int kt = 0; kt < 64; kt++) {
        wB[2 * kt]     = f2tf(wrow[kt * 8 + (lane & 3)]);
        wB[2 * kt + 1] = f2tf(wrow[kt * 8 + (lane & 3) + 4]);
    }

    // update-phase ownership: thread -> (batch ub, unit u0+uj)
    int ub = tid & 15;
    int uj = tid >> 4;
    int len = lengths[ub];
    float hreg = 0.f, creg = 0.f;

    // C-fragment coordinates for xg prefetch (warp w)
    int cn0 = dir * 2048 + w * 512 + u0 + 2 * (lane & 3);
    int cb0 = lane >> 2;

    #pragma unroll 1
    for (int t = 0; t < SEQ; t++) {
        int s = dir ? (SEQ - 1 - t) : t;

        // prefetch xg directly into mma accumulators (bias already folded in)
        const float* xg = g_XG + ((size_t)s * NXG + cn0) * 16 + cb0;
        float c0 = xg[0];
        float c1 = xg[16];
        float c2 = xg[8];
        float c3 = xg[24];

        // stage h(t-1) from global ping-pong buffer into smem (tf32-rounded)
        {
            int rp = (t + 1) & 1;
            const float4* src = (const float4*)&g_h[rp][dir][0][0];
            #pragma unroll
            for (int r = 0; r < 16; r++) {
                int f4 = r * 128 + tid;          // 0..2047
                int b = f4 >> 7;
                int k4 = f4 & 127;
                float4 v = __ldcg(src + f4);
                float4 o;
                o.x = __uint_as_float(f2tf(v.x));
                o.y = __uint_as_float(f2tf(v.y));
                o.z = __uint_as_float(f2tf(v.z));
                o.w = __uint_as_float(f2tf(v.w));
                *(float4*)(&hs[b * 516 + k4 * 4]) = o;
            }
        }
        __syncthreads();

        // gates += h @ Whh^T  (64 ktiles of m16n8k8)
        #pragma unroll
        for (int kt = 0; kt < 64; kt++) {
            const float* hb = &hs[(lane >> 2) * 516 + kt * 8 + (lane & 3)];
            unsigned a0 = __float_as_uint(hb[0]);
            unsigned a1 = __float_as_uint(hb[8 * 516]);
            unsigned a2 = __float_as_uint(hb[4]);
            unsigned a3 = __float_as_uint(hb[8 * 516 + 4]);
            mma_tf32(c0, c1, c2, c3, a0, a1, a2, a3, wB[2 * kt], wB[2 * kt + 1]);
        }

        // exchange gates within CTA
        smg[w][lane >> 2][2 * (lane & 3)]           = c0;
        smg[w][lane >> 2][2 * (lane & 3) + 1]       = c1;
        smg[w][(lane >> 2) + 8][2 * (lane & 3)]     = c2;
        smg[w][(lane >> 2) + 8][2 * (lane & 3) + 1] = c3;
        __syncthreads();

        float gi = sigm(smg[0][ub][uj]);
        float gf = sigm(smg[1][ub][uj]);
        float gg = tanhf(smg[2][ub][uj]);
        float go = sigm(smg[3][ub][uj]);
        float cn = gf * creg + gi * gg;
        float hn = go * tanhf(cn);
        bool active = s < len;
        float y = active ? hn : 0.f;
        if (active) { creg = cn; hreg = hn; }

        g_Y[(size_t)(s * 16 + ub) * HIDN + dir * 512 + u0 + uj] = y;
        __stcg(&g_h[t & 1][dir][ub][u0 + uj], hreg);

        // grid barrier (monotone counter)
        __threadfence();
        __syncthreads();
        if (tid == 0) {
            atomicAdd(&g_bar, 1u);
            unsigned target = (unsigned)(t + 1) * 128u;
            unsigned v;
            do {
                asm volatile("ld.acquire.gpu.u32 %0, [%1];" : "=r"(v) : "l"(&g_bar));
            } while (v < target);
        }
        __syncthreads();
    }
}

// ---------------- head: out[b][s][c] = a2[m] . W3[c] + b3[c] ----------------
__global__ void k_head(const float* __restrict__ W3, const float* __restrict__ b3,
                       float* __restrict__ out) {
    int gw = (blockIdx.x * blockDim.x + threadIdx.x) >> 5;
    int lane = threadIdx.x & 31;
    if (gw >= MTOT) return;
    const float* a = g_A2 + (size_t)gw * HIDN;
    float s0 = 0, s1 = 0, s2 = 0, s3 = 0, s4 = 0;
    for (int k = lane; k < HIDN; k += 32) {
        float v = a[k];
        s0 += v * W3[k];
        s1 += v * W3[1024 + k];
        s2 += v * W3[2048 + k];
        s3 += v * W3[3072 + k];
        s4 += v * W3[4096 + k];
    }
    #pragma unroll
    for (int o = 16; o; o >>= 1) {
        s0 += __shfl_down_sync(0xffffffffu, s0, o);
        s1 += __shfl_down_sync(0xffffffffu, s1, o);
        s2 += __shfl_down_sync(0xffffffffu, s2, o);
        s3 += __shfl_down_sync(0xffffffffu, s3, o);
        s4 += __shfl_down_sync(0xffffffffu, s4, o);
    }
    if (lane == 0) {
        int b = gw & 15, s = gw >> 4;
        float* o = out + ((size_t)b * SEQ + s) * 5;
        o[0] = s0 + b3[0];
        o[1] = s1 + b3[1];
        o[2] = s2 + b3[2];
        o[3] = s3 + b3[3];
        o[4] = s4 + b3[4];
    }
}

// ---------------- launch ----------------
extern "C" void kernel_launch(void* const* d_in, const int* in_sizes, int n_in,
                              void* d_out, int out_size) {
    const int*   x    = (const int*)d_in[0];
    const int*   len  = (const int*)d_in[1];
    const float* lang = (const float*)d_in[2];
    const float* emb  = (const float*)d_in[3];
    const float* W_ih = (const float*)d_in[4];   // [2][2][2048][1024]
    const float* W_hh = (const float*)d_in[5];   // [2][2][2048][512]
    const float* b_ih = (const float*)d_in[6];   // [2][2][2048]
    const float* b_hh = (const float*)d_in[7];
    const float* W1   = (const float*)d_in[8];
    const float* b1   = (const float*)d_in[9];
    const float* W2   = (const float*)d_in[10];
    const float* b2   = (const float*)d_in[11];
    const float* W3   = (const float*)d_in[12];
    const float* b3   = (const float*)d_in[13];
    float* out = (float*)d_out;

    k_embed<<<MTOT, 256>>>(x, lang, emb);

    for (int l = 0; l < 2; l++) {
        k_pre<<<128, 256>>>();
        k_bias<<<16, 256>>>(b_ih + (size_t)l * NXG, b_hh + (size_t)l * NXG);
        // XG = A @ W_ih[l]^T + bias  (A: X0 for l=0, Y for l=1), XG layout
        k_gemm<<<dim3(NXG / 128, MTOT / 128), 256>>>(
            l == 0 ? 0 : 1, W_ih + (size_t)l * 2 * 2048 * 1024, nullptr, 4, NXG, 0, 1);
        k_rec<<<128, 128>>>(W_hh + (size_t)l * 2 * 2048 * 512, len);
    }

    // MLP
    k_gemm<<<dim3(HIDN / 128, MTOT / 128), 256>>>(1, W1, b1, 2, HIDN, 1, 0);
    k_gemm<<<dim3(HIDN / 128, MTOT / 128), 256>>>(2, W2, b2, 3, HIDN, 1, 0);
    k_head<<<MTOT / 8, 256>>>(W3, b3, out);
}